// round 14
// baseline (speedup 1.0000x reference)
#include <cuda_runtime.h>
#include <cuda_fp16.h>
#include <math.h>
#include <stdint.h>

#define B_ 4
#define T_ 1024
#define C_ 1024
#define H_ 16
#define HS_ 64
#define L_ 12
#define V_ 50304
#define M_ 4096  // B*T

static const size_t NLOGITS = (size_t)M_ * V_;

// ---------------- scratch (device globals; no allocs allowed) ----------------
__device__ float g_x[(size_t)M_ * C_];
__device__ float g_loss_acc;

__device__ __half g_qkv[(size_t)M_ * 3 * C_];
__device__ __half g_h[(size_t)M_ * C_];
__device__ __half g_att[(size_t)M_ * C_];
__device__ __half g_mlp[(size_t)M_ * 4 * C_];
__device__ __half g_wT[(size_t)V_ * C_];

// ---------------- helpers ----------------
__device__ __forceinline__ uint32_t smem_u32(const void* p) {
    uint32_t a;
    asm("{ .reg .u64 t; cvta.to.shared.u64 t, %1; cvt.u32.u64 %0, t; }" : "=r"(a) : "l"(p));
    return a;
}
#define CP16(dst, src) asm volatile("cp.async.cg.shared.global [%0], [%1], 16;" :: "r"(dst), "l"(src) : "memory")
#define CP_COMMIT() asm volatile("cp.async.commit_group;" ::: "memory")
#define CP_WAIT(n)  asm volatile("cp.async.wait_group %0;" :: "n"(n) : "memory")

__device__ __forceinline__ uint32_t packh2(float x, float y) {
    __half2 t = __halves2half2(__float2half_rn(x), __float2half_rn(y));
    return *(uint32_t*)&t;
}

__device__ __forceinline__ void mma_f16(float* c, const uint32_t* a, const uint32_t* b) {
    asm volatile(
        "mma.sync.aligned.m16n8k16.row.col.f32.f16.f16.f32 "
        "{%0,%1,%2,%3}, {%4,%5,%6,%7}, {%8,%9}, {%0,%1,%2,%3};"
        : "+f"(c[0]), "+f"(c[1]), "+f"(c[2]), "+f"(c[3])
        : "r"(a[0]), "r"(a[1]), "r"(a[2]), "r"(a[3]), "r"(b[0]), "r"(b[1]));
}

__device__ __forceinline__ void ldm_x4(uint32_t* r, uint32_t addr) {
    asm volatile("ldmatrix.sync.aligned.m8n8.x4.shared.b16 {%0,%1,%2,%3}, [%4];"
        : "=r"(r[0]), "=r"(r[1]), "=r"(r[2]), "=r"(r[3]) : "r"(addr));
}
__device__ __forceinline__ void ldm_x4_t(uint32_t* r, uint32_t addr) {
    asm volatile("ldmatrix.sync.aligned.m8n8.x4.trans.shared.b16 {%0,%1,%2,%3}, [%4];"
        : "=r"(r[0]), "=r"(r[1]), "=r"(r[2]), "=r"(r[3]) : "r"(addr));
}

// ---------------- weight convert + transpose: W[K][N] -> wT[N][K] fp16 ----------------
__global__ void __launch_bounds__(256) convw_kernel(
    const float* __restrict__ W, __half* __restrict__ wT, int K, int N)
{
    __shared__ float tile[32][33];
    int nt = blockIdx.x * 32, kt = blockIdx.y * 32;
    int tx = threadIdx.x & 31, ty = threadIdx.x >> 5;
    #pragma unroll
    for (int j = 0; j < 4; j++) {
        int kk = ty + j * 8;
        tile[kk][tx] = W[(size_t)(kt + kk) * N + nt + tx];
    }
    __syncthreads();
    #pragma unroll
    for (int j = 0; j < 4; j++) {
        int nn = ty + j * 8;
        wT[(size_t)(nt + nn) * K + kt + tx] = __float2half_rn(tile[tx][nn]);
    }
}

// fused QKV weight convert: z selects Wq/Wk/Wv (all C x C)
__global__ void __launch_bounds__(256) convw3_kernel(
    const float* __restrict__ Wq, const float* __restrict__ Wk,
    const float* __restrict__ Wv, __half* __restrict__ wT)
{
    __shared__ float tile[32][33];
    int z = blockIdx.z;
    const float* W = (z == 0) ? Wq : (z == 1) ? Wk : Wv;
    __half* out = wT + (size_t)z * C_ * C_;
    int nt = blockIdx.x * 32, kt = blockIdx.y * 32;
    int tx = threadIdx.x & 31, ty = threadIdx.x >> 5;
    #pragma unroll
    for (int j = 0; j < 4; j++) {
        int kk = ty + j * 8;
        tile[kk][tx] = W[(size_t)(kt + kk) * C_ + nt + tx];
    }
    __syncthreads();
    #pragma unroll
    for (int j = 0; j < 4; j++) {
        int nn = ty + j * 8;
        out[(size_t)(nt + nn) * C_ + kt + tx] = __float2half_rn(tile[tx][nn]);
    }
}

// ---------------- fp16 1-pass GEMM via mma.sync + ldmatrix ----------------
// 128 threads, 4 warps (2x2), warp tile 64x64, CTA tile 128x128, BK=64,
// 3-stage cp.async, 2 CTAs/SM. Row stride 144B (conflict-free).
#define GROW 144
#define GTILE (128 * GROW)          // 18432
#define GSTAGE (2 * GTILE)          // 36864 (A + B)
#define GNSTAGE 3
#define GSMEM  (GNSTAGE * GSTAGE)   // 110592
__global__ void __launch_bounds__(128, 2) gemm_mma_kernel(
    const __half* __restrict__ Aw, const __half* __restrict__ Bw,
    const float* __restrict__ bias, const float* __restrict__ res,
    float* __restrict__ Cout, __half* __restrict__ Oh,
    int M, int N, int K, int relu)
{
    extern __shared__ char sm[];
    const uint32_t sbase = smem_u32(sm);
    const int tid = threadIdx.x;
    const int lane = tid & 31, wid = tid >> 5;
    const int wm = wid >> 1, wn = wid & 1;          // 2 x 2 warps
    const int g = lane >> 2, tig = lane & 3;
    const int bm = blockIdx.y << 7, bn = blockIdx.x << 7;

    const uint32_t aoff = (uint32_t)((wm * 64 + (lane & 15)) * GROW + (lane >> 4) * 16);
    const uint32_t boff = (uint32_t)((wn * 64 + (lane & 7) + ((lane >> 4) << 3)) * GROW + ((lane >> 3) & 1) * 16);

    float acc[4][8][4];
    #pragma unroll
    for (int a = 0; a < 4; a++)
        #pragma unroll
        for (int b = 0; b < 8; b++)
            #pragma unroll
            for (int c = 0; c < 4; c++) acc[a][b][c] = 0.f;

    const int nIter = K >> 6;

    auto stage = [&](int it) {
        const uint32_t s0 = sbase + (uint32_t)(it % GNSTAGE) * GSTAGE;
        const int k0 = it << 6;
        #pragma unroll
        for (int j = 0; j < 8; j++) {
            int c = tid + j * 128;          // 0..1023 chunk id
            int row = c >> 3, q = c & 7;
            uint32_t d = (uint32_t)(row * GROW + q * 16);
            size_t ga = (size_t)(bm + row) * K + k0 + q * 8;
            size_t gb = (size_t)(bn + row) * K + k0 + q * 8;
            CP16(s0 + d, Aw + ga);
            CP16(s0 + GTILE + d, Bw + gb);
        }
    };

    stage(0); CP_COMMIT();
    if (nIter > 1) { stage(1); CP_COMMIT(); }

    for (int i = 0; i < nIter; i++) {
        if (i + 1 < nIter) { CP_WAIT(1); } else { CP_WAIT(0); }
        __syncthreads();
        if (i + 2 < nIter) { stage(i + 2); CP_COMMIT(); }

        const uint32_t s0 = sbase + (uint32_t)(i % GNSTAGE) * GSTAGE;
        #pragma unroll
        for (int ks = 0; ks < 4; ks++) {
            const uint32_t kofs = (uint32_t)(ks * 32);
            uint32_t ah[4][4], bh[8][2];
            #pragma unroll
            for (int mf = 0; mf < 4; mf++)
                ldm_x4(ah[mf], s0 + aoff + (uint32_t)(mf * 16 * GROW) + kofs);
            #pragma unroll
            for (int p = 0; p < 4; p++) {
                uint32_t r[4];
                ldm_x4(r, s0 + GTILE + boff + (uint32_t)(p * 16 * GROW) + kofs);
                bh[2 * p][0] = r[0]; bh[2 * p][1] = r[1];
                bh[2 * p + 1][0] = r[2]; bh[2 * p + 1][1] = r[3];
            }
            #pragma unroll
            for (int mf = 0; mf < 4; mf++)
                #pragma unroll
                for (int nf = 0; nf < 8; nf++)
                    mma_f16(acc[mf][nf], ah[mf], bh[nf]);
        }
    }

    #pragma unroll
    for (int nf = 0; nf < 8; nf++) {
        int col = bn + wn * 64 + nf * 8 + 2 * tig;
        float2 bz = make_float2(0.f, 0.f);
        if (bias) bz = *(const float2*)(bias + col);
        #pragma unroll
        for (int mf = 0; mf < 4; mf++) {
            int row0 = bm + wm * 64 + mf * 16 + g;
            int row1 = row0 + 8;
            float c0 = acc[mf][nf][0] + bz.x;
            float c1 = acc[mf][nf][1] + bz.y;
            float c2 = acc[mf][nf][2] + bz.x;
            float c3 = acc[mf][nf][3] + bz.y;
            if (res) {
                float2 r0 = *(const float2*)(res + (size_t)row0 * N + col);
                float2 r1 = *(const float2*)(res + (size_t)row1 * N + col);
                c0 += r0.x; c1 += r0.y; c2 += r1.x; c3 += r1.y;
            }
            if (relu) {
                c0 = fmaxf(c0, 0.f); c1 = fmaxf(c1, 0.f);
                c2 = fmaxf(c2, 0.f); c3 = fmaxf(c3, 0.f);
            }
            if (Cout) {
                *(float2*)(Cout + (size_t)row0 * N + col) = make_float2(c0, c1);
                *(float2*)(Cout + (size_t)row1 * N + col) = make_float2(c2, c3);
            }
            if (Oh) {
                *(uint32_t*)(Oh + (size_t)row0 * N + col) = packh2(c0, c1);
                *(uint32_t*)(Oh + (size_t)row1 * N + col) = packh2(c2, c3);
            }
        }
    }
}

// ---------------- embedding ----------------
__global__ void __launch_bounds__(256) embed_kernel(
    const int* __restrict__ idx, const float* __restrict__ tok,
    const float* __restrict__ pos, float* __restrict__ x)
{
    int row = blockIdx.x;
    int t = row & (T_ - 1);
    int token = idx[row];
    int c = threadIdx.x * 4;
    float4 a = *(const float4*)(tok + (size_t)token * C_ + c);
    float4 p = *(const float4*)(pos + (size_t)t * C_ + c);
    *(float4*)(x + (size_t)row * C_ + c) = make_float4(a.x + p.x, a.y + p.y, a.z + p.z, a.w + p.w);
}

// ---------------- layernorm -> fp16 ----------------
__global__ void __launch_bounds__(256) ln_kernel(
    const float* __restrict__ x, const float* __restrict__ g,
    const float* __restrict__ b, __half* __restrict__ y)
{
    __shared__ float red[256];
    int row = blockIdx.x;
    int t = threadIdx.x;
    const float* xr = x + (size_t)row * C_;
    float4 v = *(const float4*)(xr + t * 4);
    red[t] = v.x + v.y + v.z + v.w;
    __syncthreads();
    for (int o = 128; o > 0; o >>= 1) { if (t < o) red[t] += red[t + o]; __syncthreads(); }
    float mean = red[0] * (1.f / C_);
    __syncthreads();
    float dx = v.x - mean, dy = v.y - mean, dz = v.z - mean, dw = v.w - mean;
    red[t] = dx * dx + dy * dy + dz * dz + dw * dw;
    __syncthreads();
    for (int o = 128; o > 0; o >>= 1) { if (t < o) red[t] += red[t + o]; __syncthreads(); }
    float inv = rsqrtf(red[0] * (1.f / C_) + 1e-5f);
    float4 gv = *(const float4*)(g + t * 4);
    float4 bv = *(const float4*)(b + t * 4);
    float o0 = dx * inv * gv.x + bv.x;
    float o1 = dy * inv * gv.y + bv.y;
    float o2 = dz * inv * gv.z + bv.z;
    float o3 = dw * inv * gv.w + bv.w;
    size_t off = (size_t)row * C_ + t * 4;
    *(uint32_t*)(y + off)     = packh2(o0, o1);
    *(uint32_t*)(y + off + 2) = packh2(o2, o3);
}

// ---------------- fused flash attention (q,k,v exact fp16, att out fp16) ----------------
#define FSTAGE 18432   // K 9216 + V 9216
#define FSMEM  (2 * FSTAGE + 9216)  // + Qh
__global__ void __launch_bounds__(128) flash_attn_kernel(
    const __half* __restrict__ qkv, __half* __restrict__ att)
{
    extern __shared__ char fsm[];
    const uint32_t sbase = smem_u32(fsm);
    const uint32_t sQ = sbase + 2 * FSTAGE;
    const int qt = blockIdx.x << 6;
    const int bh = blockIdx.y;
    const int b = bh >> 4, h = bh & 15;
    const int tid = threadIdx.x, lane = tid & 31, wid = tid >> 5;
    const int RS = 3 * C_;
    const int g = lane >> 2, tig = lane & 3;
    const int nk = (qt >> 6) + 1;

    #pragma unroll
    for (int j = 0; j < 4; j++) {
        int c = tid + j * 128;
        int row = c >> 3, q8 = c & 7;
        uint32_t d = (uint32_t)(row * 144 + q8 * 16);
        size_t gq = (size_t)(b * T_ + qt + row) * RS + h * HS_ + q8 * 8;
        CP16(sQ + d, qkv + gq);
    }

    auto stage = [&](int it) {
        const uint32_t s0 = sbase + (uint32_t)(it & 1) * FSTAGE;
        const int kt = it << 6;
        #pragma unroll
        for (int j = 0; j < 4; j++) {
            int c = tid + j * 128;
            int row = c >> 3, q8 = c & 7;
            uint32_t d = (uint32_t)(row * 144 + q8 * 16);
            size_t gk = (size_t)(b * T_ + kt + row) * RS + C_ + h * HS_ + q8 * 8;
            size_t gv = (size_t)(b * T_ + kt + row) * RS + 2 * C_ + h * HS_ + q8 * 8;
            CP16(s0 + d, qkv + gk);
            CP16(s0 + 9216 + d, qkv + gv);
        }
    };

    stage(0); CP_COMMIT();

    const uint32_t aoff = (uint32_t)((wid * 16 + (lane & 15)) * 144 + (lane >> 4) * 16);
    const uint32_t koff = (uint32_t)(((lane & 7) + ((lane >> 4) << 3)) * 144 + ((lane >> 3) & 1) * 16);
    const uint32_t voff = (uint32_t)((lane & 15) * 144 + (lane >> 4) * 16);

    float m0 = -INFINITY, m1 = -INFINITY, l0 = 0.f, l1 = 0.f;
    float accO[8][4];
    #pragma unroll
    for (int n = 0; n < 8; n++)
        #pragma unroll
        for (int c = 0; c < 4; c++) accO[n][c] = 0.f;

    uint32_t qhf[4][4];
    bool qloaded = false;

    for (int i = 0; i < nk; i++) {
        if (i + 1 < nk) { stage(i + 1); CP_COMMIT(); CP_WAIT(1); } else { CP_WAIT(0); }
        __syncthreads();
        if (!qloaded) {
            #pragma unroll
            for (int kc = 0; kc < 4; kc++)
                ldm_x4(qhf[kc], sQ + aoff + kc * 32);
            qloaded = true;
        }
        const uint32_t s0 = sbase + (uint32_t)(i & 1) * FSTAGE;

        float acc[8][4];
        #pragma unroll
        for (int n = 0; n < 8; n++)
            #pragma unroll
            for (int c = 0; c < 4; c++) acc[n][c] = 0.f;
        #pragma unroll
        for (int kc = 0; kc < 4; kc++) {
            uint32_t bb[8][2];
            #pragma unroll
            for (int p = 0; p < 4; p++) {
                uint32_t r[4];
                ldm_x4(r, s0 + koff + (uint32_t)(p * 16 * 144) + kc * 32);
                bb[2 * p][0] = r[0]; bb[2 * p][1] = r[1];
                bb[2 * p + 1][0] = r[2]; bb[2 * p + 1][1] = r[3];
            }
            #pragma unroll
            for (int nf = 0; nf < 8; nf++) mma_f16(acc[nf], qhf[kc], bb[nf]);
        }

        const bool diag = (i == nk - 1);
        const int lr0 = wid * 16 + g, lr1 = lr0 + 8;
        #pragma unroll
        for (int nf = 0; nf < 8; nf++) {
            int c0 = nf * 8 + 2 * tig;
            acc[nf][0] = (diag && (c0     > lr0)) ? -INFINITY : acc[nf][0] * 0.125f;
            acc[nf][1] = (diag && (c0 + 1 > lr0)) ? -INFINITY : acc[nf][1] * 0.125f;
            acc[nf][2] = (diag && (c0     > lr1)) ? -INFINITY : acc[nf][2] * 0.125f;
            acc[nf][3] = (diag && (c0 + 1 > lr1)) ? -INFINITY : acc[nf][3] * 0.125f;
        }

        float mt0 = -INFINITY, mt1 = -INFINITY;
        #pragma unroll
        for (int nf = 0; nf < 8; nf++) {
            mt0 = fmaxf(mt0, fmaxf(acc[nf][0], acc[nf][1]));
            mt1 = fmaxf(mt1, fmaxf(acc[nf][2], acc[nf][3]));
        }
        mt0 = fmaxf(mt0, __shfl_xor_sync(0xffffffff, mt0, 1));
        mt0 = fmaxf(mt0, __shfl_xor_sync(0xffffffff, mt0, 2));
        mt1 = fmaxf(mt1, __shfl_xor_sync(0xffffffff, mt1, 1));
        mt1 = fmaxf(mt1, __shfl_xor_sync(0xffffffff, mt1, 2));
        float mn0 = fmaxf(m0, mt0), mn1 = fmaxf(m1, mt1);
        float al0 = __expf(m0 - mn0), al1 = __expf(m1 - mn1);
        float sum0 = 0.f, sum1 = 0.f;
        #pragma unroll
        for (int nf = 0; nf < 8; nf++) {
            acc[nf][0] = __expf(acc[nf][0] - mn0);
            acc[nf][1] = __expf(acc[nf][1] - mn0);
            acc[nf][2] = __expf(acc[nf][2] - mn1);
            acc[nf][3] = __expf(acc[nf][3] - mn1);
            sum0 += acc[nf][0] + acc[nf][1];
            sum1 += acc[nf][2] + acc[nf][3];
        }
        sum0 += __shfl_xor_sync(0xffffffff, sum0, 1);
        sum0 += __shfl_xor_sync(0xffffffff, sum0, 2);
        sum1 += __shfl_xor_sync(0xffffffff, sum1, 1);
        sum1 += __shfl_xor_sync(0xffffffff, sum1, 2);
        l0 = l0 * al0 + sum0;
        l1 = l1 * al1 + sum1;
        m0 = mn0; m1 = mn1;
        #pragma unroll
        for (int nf = 0; nf < 8; nf++) {
            accO[nf][0] *= al0; accO[nf][1] *= al0;
            accO[nf][2] *= al1; accO[nf][3] *= al1;
        }

        #pragma unroll
        for (int kc = 0; kc < 4; kc++) {
            uint32_t aw[4];
            aw[0] = packh2(acc[2 * kc][0],     acc[2 * kc][1]);
            aw[1] = packh2(acc[2 * kc][2],     acc[2 * kc][3]);
            aw[2] = packh2(acc[2 * kc + 1][0], acc[2 * kc + 1][1]);
            aw[3] = packh2(acc[2 * kc + 1][2], acc[2 * kc + 1][3]);
            #pragma unroll
            for (int db = 0; db < 4; db++) {
                uint32_t rh[4];
                uint32_t vaddr = s0 + 9216 + voff + (uint32_t)(kc * 16 * 144) + db * 32;
                ldm_x4_t(rh, vaddr);
                mma_f16(accO[2 * db],     aw, rh);
                mma_f16(accO[2 * db + 1], aw, rh + 2);
            }
        }
        __syncthreads();
    }

    float il0 = 1.f / l0, il1 = 1.f / l1;
    #pragma unroll
    for (int nf = 0; nf < 8; nf++) {
        int col = h * HS_ + nf * 8 + 2 * tig;
        int row0 = qt + wid * 16 + g;
        size_t off0 = (size_t)(b * T_ + row0) * C_ + col;
        size_t off1 = (size_t)(b * T_ + row0 + 8) * C_ + col;
        *(uint32_t*)(att + off0) = packh2(accO[nf][0] * il0, accO[nf][1] * il0);
        *(uint32_t*)(att + off1) = packh2(accO[nf][2] * il1, accO[nf][3] * il1);
    }
}

// ---------------- loss ----------------
__global__ void zero_acc_kernel(float* acc) { *acc = 0.f; }

__global__ void __launch_bounds__(256) loss_kernel(
    const float* __restrict__ logits, const int* __restrict__ targets, float* __restrict__ acc)
{
    __shared__ float red[256];
    int row = blockIdx.x;
    const float* lr = logits + (size_t)row * V_;
    int t = threadIdx.x;
    float mx = -INFINITY;
    for (int c = t; c < V_; c += 256) mx = fmaxf(mx, lr[c]);
    red[t] = mx; __syncthreads();
    for (int o = 128; o > 0; o >>= 1) { if (t < o) red[t] = fmaxf(red[t], red[t + o]); __syncthreads(); }
    float Mx = red[0]; __syncthreads();
    float s = 0.f;
    for (int c = t; c < V_; c += 256) s += __expf(lr[c] - Mx);
    red[t] = s; __syncthreads();
    for (int o = 128; o > 0; o >>= 1) { if (t < o) red[t] += red[t + o]; __syncthreads(); }
    if (t == 0) {
        float lse = logf(red[0]) + Mx;
        int tgt = targets[row];
        atomicAdd(acc, (lse - lr[tgt]) * (1.f / M_));
    }
}

__global__ void write_loss_kernel(const float* acc, float* out) { out[0] = *acc; }

// ---------------- launch ----------------
extern "C" void kernel_launch(void* const* d_in, const int* in_sizes, int n_in,
                              void* d_out, int out_size)
{
    const int*   idx   = (const int*)d_in[0];
    const int*   tgt   = (const int*)d_in[1];
    const float* tok   = (const float*)d_in[2];
    const float* pos   = (const float*)d_in[3];
    const float* ln1g  = (const float*)d_in[4];
    const float* ln1b  = (const float*)d_in[5];
    const float* Wq    = (const float*)d_in[6];
    const float* Wk    = (const float*)d_in[7];
    const float* Wv    = (const float*)d_in[8];
    const float* Wo    = (const float*)d_in[9];
    const float* bo    = (const float*)d_in[10];
    const float* ln2g  = (const float*)d_in[11];
    const float* ln2b  = (const float*)d_in[12];
    const float* W1    = (const float*)d_in[13];
    const float* b1    = (const float*)d_in[14];
    const float* W2    = (const float*)d_in[15];
    const float* b2    = (const float*)d_in[16];
    const float* lnfg  = (const float*)d_in[17];
    const float* lnfb  = (const float*)d_in[18];
    const float* Wlm   = (const float*)d_in[19];
    const float* blm   = (const float*)d_in[20];

    float *xb, *accp;
    __half *qk, *hb, *ab, *mb, *wt;
    cudaGetSymbolAddress((void**)&xb, g_x);
    cudaGetSymbolAddress((void**)&accp, g_loss_acc);
    cudaGetSymbolAddress((void**)&qk, g_qkv);
    cudaGetSymbolAddress((void**)&hb, g_h);
    cudaGetSymbolAddress((void**)&ab, g_att);
    cudaGetSymbolAddress((void**)&mb, g_mlp);
    cudaGetSymbolAddress((void**)&wt, g_wT);

    cudaFuncSetAttribute(gemm_mma_kernel, cudaFuncAttributeMaxDynamicSharedMemorySize, GSMEM);
    cudaFuncSetAttribute(flash_attn_kernel, cudaFuncAttributeMaxDynamicSharedMemorySize, FSMEM);

    embed_kernel<<<M_, 256>>>(idx, tok, pos, xb);

    dim3 gC(C_ / 128, M_ / 128);
    dim3 gQKV(3 * C_ / 128, M_ / 128);
    dim3 gF(4 * C_ / 128, M_ / 128);
    dim3 gFlash(T_ / 64, B_ * H_);
    dim3 cv3(C_ / 32, C_ / 32, 3);
    dim3 cvC(C_ / 32, C_ / 32);
    dim3 cv1(4 * C_ / 32, C_ / 32);
    dim3 cv2(C_ / 32, 4 * C_ / 32);
    dim3 cvLM(V_ / 32, C_ / 32);

    for (int l = 0; l < L_; l++) {
        ln_kernel<<<M_, 256>>>(xb, ln1g + (size_t)l * C_, ln1b + (size_t)l * C_, hb);

        convw3_kernel<<<cv3, 256>>>(Wq + (size_t)l * C_ * C_, Wk + (size_t)l * C_ * C_,
                                    Wv + (size_t)l * C_ * C_, wt);
        gemm_mma_kernel<<<gQKV, 128, GSMEM>>>(hb, wt, nullptr, nullptr, nullptr, qk, M_, 3 * C_, C_, 0);

        flash_attn_kernel<<<gFlash, 128, FSMEM>>>(qk, ab);

        convw_kernel<<<cvC, 256>>>(Wo + (size_t)l * C_ * C_, wt, C_, C_);
        gemm_mma_kernel<<<gC, 128, GSMEM>>>(ab, wt, bo + (size_t)l * C_, xb, xb, nullptr, M_, C_, C_, 0);

        ln_kernel<<<M_, 256>>>(xb, ln2g + (size_t)l * C_, ln2b + (size_t)l * C_, hb);

        convw_kernel<<<cv1, 256>>>(W1 + (size_t)l * C_ * 4 * C_, wt, C_, 4 * C_);
        gemm_mma_kernel<<<gF, 128, GSMEM>>>(hb, wt, b1 + (size_t)l * 4 * C_, nullptr, nullptr, mb, M_, 4 * C_, C_, 1);
        convw_kernel<<<cv2, 256>>>(W2 + (size_t)l * 4 * C_ * C_, wt, 4 * C_, C_);
        gemm_mma_kernel<<<gC, 128, GSMEM>>>(mb, wt, b2 + (size_t)l * C_, xb, xb, nullptr, M_, C_, 4 * C_, 0);
    }

    ln_kernel<<<M_, 256>>>(xb, lnfg, lnfb, hb);

    float* out = (float*)d_out;
    convw_kernel<<<cvLM, 256>>>(Wlm, wt, C_, V_);
    dim3 gLM(V_ / 128, M_ / 128);
    gemm_mma_kernel<<<gLM, 128, GSMEM>>>(hb, wt, blm, nullptr, out, nullptr, M_, V_, C_, 0);

    if ((size_t)out_size > NLOGITS) {
        zero_acc_kernel<<<1, 1>>>(accp);
        loss_kernel<<<M_, 256>>>(out, tgt, accp);
        write_loss_kernel<<<1, 1>>>(accp, out + NLOGITS);
    }
}